// round 7
// baseline (speedup 1.0000x reference)
#include <cuda_runtime.h>
#include <cstdint>

#define CIN   64
#define COUT  64
#define HD    128
#define WD    128
#define BD    4
#define KK    9
#define HW    (HD*WD)

// ------------------------- scratch (device globals) -------------------------
__device__ float  g_xhwc[BD*HW*CIN];          // x in NHWC (16 MB)
__device__ float  g_wd1 [CIN*KK*COUT];        // w_def [c*9+k][o] plain floats
__device__ float4 g_mwgt[BD*HD*KK*WD];        // bilinear weights (validity folded)
__device__ int4   g_midx[BD*HD*KK*WD];        // tap indices, pre-multiplied by 64
__device__ unsigned long long g_woffp[576*9]; // w_off prepacked [tap*64+c][j] {wy,wx}

typedef unsigned long long ull;

__device__ __forceinline__ void fma2(ull &acc, ull a, ull b) {
    asm("fma.rn.f32x2 %0, %1, %2, %0;" : "+l"(acc) : "l"(a), "l"(b));
}
__device__ __forceinline__ ull pack2(float a, float b) {
    ull r; asm("mov.b64 %0, {%1, %2};" : "=l"(r) : "f"(a), "f"(b)); return r;
}
__device__ __forceinline__ float2 unpack2(ull v) {
    float2 r; asm("mov.b64 {%0, %1}, %2;" : "=f"(r.x), "=f"(r.y) : "l"(v)); return r;
}

// ------------------------- kernel: NCHW -> NHWC -----------------------------
__global__ __launch_bounds__(256)
void k_tr(const float* __restrict__ x) {
    __shared__ float tile[64][65];
    int b = blockIdx.y, hw0 = blockIdx.x * 64, t = threadIdx.x;
    const float* xb = x + (size_t)b * CIN * HW;
    #pragma unroll
    for (int it = 0; it < 16; ++it) {
        int id = t + it * 256;
        int c = id >> 6, i = id & 63;
        tile[c][i] = xb[c * HW + hw0 + i];
    }
    __syncthreads();
    float* ob = g_xhwc + (size_t)b * HW * CIN + (size_t)hw0 * CIN;
    #pragma unroll
    for (int it = 0; it < 16; ++it) {
        int id = t + it * 256;
        int i = id >> 6, c = id & 63;
        ob[id] = tile[c][i];
    }
}

// --------------------- prepack w_def (plain, [c*9+k][o]) --------------------
__global__ void k_prep_w(const float* __restrict__ w_def) {
    int id = blockIdx.x * 256 + threadIdx.x;      // 0 .. 36863
    if (id >= CIN * KK * COUT) return;
    int o  = id & 63;
    int ck = id >> 6;                              // c*9 + k
    int c  = ck / 9, k = ck - c * 9;
    g_wd1[id] = w_def[(o * CIN + c) * KK + k];
}

// --------------------- prepack w_off (paired {wy,wx}) -----------------------
__global__ void k_prep_off(const float* __restrict__ w_off) {
    int id = blockIdx.x * 256 + threadIdx.x;      // 0 .. 5183
    if (id >= 576 * 9) return;
    int grp = id / 9, j = id - grp * 9;
    int tap = grp >> 6, c = grp & 63;
    float wa = w_off[((2 * j    ) * CIN + c) * KK + tap];
    float wb = w_off[((2 * j + 1) * CIN + c) * KK + tap];
    g_woffp[id] = pack2(wa, wb);
}

// ------------- kernel: offset conv + bilinear metadata ----------------------
// grid (HD, BD), 128 threads (thread = w)
__global__ __launch_bounds__(128)
void k_off(const float* __restrict__ x, const float* __restrict__ b_off) {
    __shared__ ull woffp[576 * 10];   // [tap*64+c][j], padded to 10
    int h = blockIdx.x, b = blockIdx.y, t = threadIdx.x;

    for (int id = t; id < 576 * 9; id += 128) {
        int grp = id / 9, j = id - grp * 9;
        woffp[grp * 10 + j] = g_woffp[id];
    }
    __syncthreads();

    ull acc[9];
    #pragma unroll
    for (int j = 0; j < 9; ++j) acc[j] = 0ULL;

    const float* xb = x + (size_t)b * CIN * HW;
    #pragma unroll
    for (int tap = 0; tap < 9; ++tap) {
        int dy = tap / 3 - 1, dx = tap % 3 - 1;
        int hy = h + dy;
        if (hy < 0 || hy >= HD) continue;
        int wx = t + dx;
        bool vx = (wx >= 0) && (wx < WD);
        const float* xr = xb + hy * WD + wx;
        const ull* wp0 = woffp + tap * 64 * 10;
        #pragma unroll 4
        for (int c = 0; c < 64; ++c) {
            float xv = vx ? xr[c * HW] : 0.f;
            ull xp = pack2(xv, xv);
            const ull* wp = wp0 + c * 10;
            ulonglong2 q0 = *(const ulonglong2*)(wp);
            ulonglong2 q1 = *(const ulonglong2*)(wp + 2);
            ulonglong2 q2 = *(const ulonglong2*)(wp + 4);
            ulonglong2 q3 = *(const ulonglong2*)(wp + 6);
            ull        q8 = wp[8];
            fma2(acc[0], xp, q0.x); fma2(acc[1], xp, q0.y);
            fma2(acc[2], xp, q1.x); fma2(acc[3], xp, q1.y);
            fma2(acc[4], xp, q2.x); fma2(acc[5], xp, q2.y);
            fma2(acc[6], xp, q3.x); fma2(acc[7], xp, q3.y);
            fma2(acc[8], xp, q8);
        }
    }

    int base = ((b * HD + h) * KK) * WD + t;
    #pragma unroll
    for (int k = 0; k < 9; ++k) {
        float2 o2 = unpack2(acc[k]);
        float dy  = o2.x + b_off[2 * k];
        float dxo = o2.y + b_off[2 * k + 1];
        float py = (float)(h - 1 + k / 3) + dy;
        float px = (float)(t - 1 + k % 3) + dxo;
        float y0f = floorf(py), x0f = floorf(px);
        float fy = py - y0f, fx = px - x0f;
        int y0 = (int)y0f, x0 = (int)x0f;
        int y1 = y0 + 1, x1 = x0 + 1;
        float vy0 = (y0 >= 0 && y0 < HD) ? 1.f : 0.f;
        float vy1 = (y1 >= 0 && y1 < HD) ? 1.f : 0.f;
        float vx0 = (x0 >= 0 && x0 < WD) ? 1.f : 0.f;
        float vx1 = (x1 >= 0 && x1 < WD) ? 1.f : 0.f;
        float w00 = (1.f - fy) * (1.f - fx) * vy0 * vx0;
        float w01 = (1.f - fy) * fx         * vy0 * vx1;
        float w10 = fy * (1.f - fx)         * vy1 * vx0;
        float w11 = fy * fx                 * vy1 * vx1;
        int cy0 = min(max(y0, 0), HD - 1), cy1 = min(max(y1, 0), HD - 1);
        int cx0 = min(max(x0, 0), WD - 1), cx1 = min(max(x1, 0), WD - 1);
        g_mwgt[base + k * WD] = make_float4(w00, w01, w10, w11);
        g_midx[base + k * WD] = make_int4((cy0 * WD + cx0) * CIN,
                                          (cy0 * WD + cx1) * CIN,
                                          (cy1 * WD + cx0) * CIN,
                                          (cy1 * WD + cx1) * CIN);
    }
}

// ---------------- main: sample + 64x576 GEMM per pixel ----------------------
// grid (HD, BD) = one row of 128 px per CTA, 128 threads, thread = 8px x 8out
// Gather granularity: 16 channels (144 S rows) per pass; GEMM in two 72-row
// halves with a single W buffer restaged between halves.
#define SROW  132                      // S row stride (floats): conflict-free
#define WROW  96                       // W row stride: 8 groups of (8 + 4 pad)
#define S_FLOATS (144 * SROW)          // 19008
#define W_FLOATS (72 * WROW)           // 6912
#define SMEM_MAIN ((S_FLOATS + W_FLOATS) * 4)   // 103,680 B -> 2 CTAs/SM

__global__ __launch_bounds__(128)
void k_main(float* __restrict__ out) {
    extern __shared__ float smem[];
    float* S  = smem;                  // [144][132]
    float* W1 = smem + S_FLOATS;       // [72][96]

    int h = blockIdx.x, b = blockIdx.y, t = threadIdx.x;

    int c4 = t & 3,  g  = t >> 2;      // gather map: 4 channel-quads x 32 groups
    int og = t & 7,  pg = t >> 3;      // gemm map:   8 out-groups  x 16 px-groups

    ull acc[4][8];
    #pragma unroll
    for (int i = 0; i < 4; ++i)
        #pragma unroll
        for (int o = 0; o < 8; ++o) acc[i][o] = 0ULL;

    const float* xb = g_xhwc + (size_t)b * HW * CIN;
    int mbase = (b * HD + h) * KK * WD;
    const float4* mw = g_mwgt + mbase;
    const int4*   mi = g_midx + mbase;

    for (int ccp = 0; ccp < 4; ++ccp) {
        // ---- stage W for first half-chunk (independent of gather) ----------
        {
            const float* wsrc = g_wd1 + (ccp * 2) * 72 * 64;
            #pragma unroll
            for (int i = 0; i < 36; ++i) {
                int id = t + i * 128;
                int row = id >> 6, o = id & 63;
                W1[row * WROW + (o >> 3) * 12 + (o & 7)] = wsrc[id];
            }
        }

        // ---- gather 16 channels: 4 lanes x LDG.128 per tap-corner ----------
        const float* xq = xb + ccp * 16 + c4 * 4;
        #pragma unroll 2
        for (int it = 0; it < 36; ++it) {
            int pi = it * 32 + g;                  // k*128 + p
            float4 wg = mw[pi];
            int4   ii = mi[pi];
            ulonglong2 v00 = *(const ulonglong2*)(xq + ii.x);
            ulonglong2 v01 = *(const ulonglong2*)(xq + ii.y);
            ulonglong2 v10 = *(const ulonglong2*)(xq + ii.z);
            ulonglong2 v11 = *(const ulonglong2*)(xq + ii.w);
            ull w00 = pack2(wg.x, wg.x), w01p = pack2(wg.y, wg.y);
            ull w10p = pack2(wg.z, wg.z), w11p = pack2(wg.w, wg.w);
            ull slo = 0ULL, shi = 0ULL;
            fma2(slo, v00.x, w00);  fma2(shi, v00.y, w00);
            fma2(slo, v01.x, w01p); fma2(shi, v01.y, w01p);
            fma2(slo, v10.x, w10p); fma2(shi, v10.y, w10p);
            fma2(slo, v11.x, w11p); fma2(shi, v11.y, w11p);
            float2 a = unpack2(slo), bb = unpack2(shi);
            int k = pi >> 7, p = pi & 127;
            float* sp = S + ((c4 * 4) * KK + k) * SROW + p;
            sp[0]             = a.x;
            sp[ 9 * SROW]     = a.y;
            sp[18 * SROW]     = bb.x;
            sp[27 * SROW]     = bb.y;
        }
        __syncthreads();

        // ---- GEMM over the two 72-row halves -------------------------------
        #pragma unroll
        for (int half = 0; half < 2; ++half) {
            const float* srow = S + half * 72 * SROW + pg * 8;
            const float* wrow = W1 + og * 12;
            #pragma unroll 2
            for (int row = 0; row < 72; ++row) {
                ulonglong2 s01 = *(const ulonglong2*)(srow + row * SROW);
                ulonglong2 s23 = *(const ulonglong2*)(srow + row * SROW + 4);
                float4 wa = *(const float4*)(wrow + row * WROW);
                float4 wb = *(const float4*)(wrow + row * WROW + 4);
                ull w0 = pack2(wa.x, wa.x), w1 = pack2(wa.y, wa.y);
                ull w2 = pack2(wa.z, wa.z), w3 = pack2(wa.w, wa.w);
                ull w4 = pack2(wb.x, wb.x), w5 = pack2(wb.y, wb.y);
                ull w6 = pack2(wb.z, wb.z), w7 = pack2(wb.w, wb.w);
                fma2(acc[0][0], s01.x, w0); fma2(acc[1][0], s01.y, w0);
                fma2(acc[2][0], s23.x, w0); fma2(acc[3][0], s23.y, w0);
                fma2(acc[0][1], s01.x, w1); fma2(acc[1][1], s01.y, w1);
                fma2(acc[2][1], s23.x, w1); fma2(acc[3][1], s23.y, w1);
                fma2(acc[0][2], s01.x, w2); fma2(acc[1][2], s01.y, w2);
                fma2(acc[2][2], s23.x, w2); fma2(acc[3][2], s23.y, w2);
                fma2(acc[0][3], s01.x, w3); fma2(acc[1][3], s01.y, w3);
                fma2(acc[2][3], s23.x, w3); fma2(acc[3][3], s23.y, w3);
                fma2(acc[0][4], s01.x, w4); fma2(acc[1][4], s01.y, w4);
                fma2(acc[2][4], s23.x, w4); fma2(acc[3][4], s23.y, w4);
                fma2(acc[0][5], s01.x, w5); fma2(acc[1][5], s01.y, w5);
                fma2(acc[2][5], s23.x, w5); fma2(acc[3][5], s23.y, w5);
                fma2(acc[0][6], s01.x, w6); fma2(acc[1][6], s01.y, w6);
                fma2(acc[2][6], s23.x, w6); fma2(acc[3][6], s23.y, w6);
                fma2(acc[0][7], s01.x, w7); fma2(acc[1][7], s01.y, w7);
                fma2(acc[2][7], s23.x, w7); fma2(acc[3][7], s23.y, w7);
            }
            __syncthreads();
            if (half == 0) {
                // restage W for second half-chunk
                const float* wsrc = g_wd1 + (ccp * 2 + 1) * 72 * 64;
                #pragma unroll
                for (int i = 0; i < 36; ++i) {
                    int id = t + i * 128;
                    int row = id >> 6, o = id & 63;
                    W1[row * WROW + (o >> 3) * 12 + (o & 7)] = wsrc[id];
                }
                __syncthreads();
            }
        }
    }

    // ---- epilogue: out[b][og*8+o][h][pg*8 .. +7] ----------------------------
    float* op = out + (((size_t)(b * COUT + og * 8) * HD + h) * WD) + pg * 8;
    #pragma unroll
    for (int o = 0; o < 8; ++o) {
        float2 a0 = unpack2(acc[0][o]);
        float2 a1 = unpack2(acc[1][o]);
        float2 a2 = unpack2(acc[2][o]);
        float2 a3 = unpack2(acc[3][o]);
        *(float4*)(op + (size_t)o * HW)     = make_float4(a0.x, a0.y, a1.x, a1.y);
        *(float4*)(op + (size_t)o * HW + 4) = make_float4(a2.x, a2.y, a3.x, a3.y);
    }
}

// ------------------------------- launch -------------------------------------
extern "C" void kernel_launch(void* const* d_in, const int* in_sizes, int n_in,
                              void* d_out, int out_size) {
    const float* x     = (const float*)d_in[0];
    const float* w_off = (const float*)d_in[1];
    const float* b_off = (const float*)d_in[2];
    const float* w_def = (const float*)d_in[3];
    float* out = (float*)d_out;

    cudaFuncSetAttribute(k_main, cudaFuncAttributeMaxDynamicSharedMemorySize, SMEM_MAIN);

    k_tr      <<<dim3(HW / 64, BD), 256>>>(x);
    k_prep_w  <<<(CIN * KK * COUT + 255) / 256, 256>>>(w_def);
    k_prep_off<<<(576 * 9 + 255) / 256, 256>>>(w_off);
    k_off     <<<dim3(HD, BD), 128>>>(x, b_off);
    k_main    <<<dim3(HD, BD), 128, SMEM_MAIN>>>(out);
}

// round 10
// speedup vs baseline: 1.2554x; 1.2554x over previous
#include <cuda_runtime.h>
#include <cstdint>

#define CIN   64
#define COUT  64
#define HD    128
#define WD    128
#define BD    4
#define KK    9
#define HW    (HD*WD)

// ------------------------- scratch (device globals) -------------------------
__device__ float  g_xhwc[BD*HW*CIN];          // x in NHWC (16 MB)
__device__ float  g_wd1 [CIN*KK*COUT];        // w_def [c*9+k][o] plain floats
__device__ float4 g_mwgt[BD*HD*KK*WD];        // bilinear weights (validity folded)
__device__ int4   g_midx[BD*HD*KK*WD];        // tap indices, pre-multiplied by 64
__device__ unsigned long long g_woffp[576*9]; // w_off prepacked [tap*64+c][j] {wy,wx}

typedef unsigned long long ull;

__device__ __forceinline__ void fma2(ull &acc, ull a, ull b) {
    asm("fma.rn.f32x2 %0, %1, %2, %0;" : "+l"(acc) : "l"(a), "l"(b));
}
__device__ __forceinline__ ull pack2(float a, float b) {
    ull r; asm("mov.b64 %0, {%1, %2};" : "=l"(r) : "f"(a), "f"(b)); return r;
}
__device__ __forceinline__ float2 unpack2(ull v) {
    float2 r; asm("mov.b64 {%0, %1}, %2;" : "=f"(r.x), "=f"(r.y) : "l"(v)); return r;
}

// ------------------------- kernel: NCHW -> NHWC -----------------------------
__global__ __launch_bounds__(256)
void k_tr(const float* __restrict__ x) {
    __shared__ float tile[64][65];
    int b = blockIdx.y, hw0 = blockIdx.x * 64, t = threadIdx.x;
    const float* xb = x + (size_t)b * CIN * HW;
    #pragma unroll
    for (int it = 0; it < 16; ++it) {
        int id = t + it * 256;
        int c = id >> 6, i = id & 63;
        tile[c][i] = xb[c * HW + hw0 + i];
    }
    __syncthreads();
    float* ob = g_xhwc + (size_t)b * HW * CIN + (size_t)hw0 * CIN;
    #pragma unroll
    for (int it = 0; it < 16; ++it) {
        int id = t + it * 256;
        int i = id >> 6, c = id & 63;
        ob[id] = tile[c][i];
    }
}

// --------------------- prepack w_def (plain, [c*9+k][o]) --------------------
__global__ void k_prep_w(const float* __restrict__ w_def) {
    int id = blockIdx.x * 256 + threadIdx.x;      // 0 .. 36863
    if (id >= CIN * KK * COUT) return;
    int o  = id & 63;
    int ck = id >> 6;                              // c*9 + k
    int c  = ck / 9, k = ck - c * 9;
    g_wd1[id] = w_def[(o * CIN + c) * KK + k];
}

// --------------------- prepack w_off (paired {wy,wx}) -----------------------
__global__ void k_prep_off(const float* __restrict__ w_off) {
    int id = blockIdx.x * 256 + threadIdx.x;      // 0 .. 5183
    if (id >= 576 * 9) return;
    int grp = id / 9, j = id - grp * 9;
    int tap = grp >> 6, c = grp & 63;
    float wa = w_off[((2 * j    ) * CIN + c) * KK + tap];
    float wb = w_off[((2 * j + 1) * CIN + c) * KK + tap];
    g_woffp[id] = pack2(wa, wb);
}

// ------------- kernel: offset conv + bilinear metadata ----------------------
// grid (HD/2, BD), 128 threads (thread = w, 2 output rows per thread)
__global__ __launch_bounds__(128)
void k_off(const float* __restrict__ x, const float* __restrict__ b_off) {
    __shared__ ull woffp[576 * 10];   // [tap*64+c][j], padded to 10 (16B align)
    int h0 = blockIdx.x * 2, b = blockIdx.y, t = threadIdx.x;

    for (int id = t; id < 576 * 9; id += 128) {
        int grp = id / 9, j = id - grp * 9;
        woffp[grp * 10 + j] = g_woffp[id];
    }
    __syncthreads();

    ull acc0[9], acc1[9];
    #pragma unroll
    for (int j = 0; j < 9; ++j) { acc0[j] = 0ULL; acc1[j] = 0ULL; }

    const float* xb = x + (size_t)b * CIN * HW;
    #pragma unroll
    for (int tap = 0; tap < 9; ++tap) {
        int ty = tap / 3, tx = tap % 3;
        int sy0 = h0 - 1 + ty;               // source row for px row h0
        int sy1 = sy0 + 1;                   // source row for px row h0+1
        bool v0 = (sy0 >= 0) && (sy0 < HD);
        bool v1 = (sy1 >= 0) && (sy1 < HD);
        if (!v0 && !v1) continue;
        int wx = t - 1 + tx;
        bool vx = (wx >= 0) && (wx < WD);
        const float* xr0 = xb + sy0 * WD + wx;
        const float* xr1 = xr0 + WD;
        const ull* wp0 = woffp + tap * 64 * 10;
        for (int c = 0; c < 64; ++c) {
            float xv0 = (v0 && vx) ? xr0[c * HW] : 0.f;
            float xv1 = (v1 && vx) ? xr1[c * HW] : 0.f;
            ull xp0 = pack2(xv0, xv0);
            ull xp1 = pack2(xv1, xv1);
            const ull* wp = wp0 + c * 10;
            ulonglong2 q0 = *(const ulonglong2*)(wp);
            ulonglong2 q1 = *(const ulonglong2*)(wp + 2);
            ulonglong2 q2 = *(const ulonglong2*)(wp + 4);
            ulonglong2 q3 = *(const ulonglong2*)(wp + 6);
            ull        q8 = wp[8];
            fma2(acc0[0], xp0, q0.x); fma2(acc1[0], xp1, q0.x);
            fma2(acc0[1], xp0, q0.y); fma2(acc1[1], xp1, q0.y);
            fma2(acc0[2], xp0, q1.x); fma2(acc1[2], xp1, q1.x);
            fma2(acc0[3], xp0, q1.y); fma2(acc1[3], xp1, q1.y);
            fma2(acc0[4], xp0, q2.x); fma2(acc1[4], xp1, q2.x);
            fma2(acc0[5], xp0, q2.y); fma2(acc1[5], xp1, q2.y);
            fma2(acc0[6], xp0, q3.x); fma2(acc1[6], xp1, q3.x);
            fma2(acc0[7], xp0, q3.y); fma2(acc1[7], xp1, q3.y);
            fma2(acc0[8], xp0, q8);   fma2(acc1[8], xp1, q8);
        }
    }

    #pragma unroll
    for (int r = 0; r < 2; ++r) {
        int h = h0 + r;
        int base = ((b * HD + h) * KK) * WD + t;
        #pragma unroll
        for (int k = 0; k < 9; ++k) {
            float2 o2 = unpack2(r == 0 ? acc0[k] : acc1[k]);
            float dy  = o2.x + b_off[2 * k];
            float dxo = o2.y + b_off[2 * k + 1];
            float py = (float)(h - 1 + k / 3) + dy;
            float px = (float)(t - 1 + k % 3) + dxo;
            float y0f = floorf(py), x0f = floorf(px);
            float fy = py - y0f, fx = px - x0f;
            int y0 = (int)y0f, x0 = (int)x0f;
            int y1 = y0 + 1, x1 = x0 + 1;
            float vy0 = (y0 >= 0 && y0 < HD) ? 1.f : 0.f;
            float vy1 = (y1 >= 0 && y1 < HD) ? 1.f : 0.f;
            float vx0 = (x0 >= 0 && x0 < WD) ? 1.f : 0.f;
            float vx1 = (x1 >= 0 && x1 < WD) ? 1.f : 0.f;
            float w00 = (1.f - fy) * (1.f - fx) * vy0 * vx0;
            float w01 = (1.f - fy) * fx         * vy0 * vx1;
            float w10 = fy * (1.f - fx)         * vy1 * vx0;
            float w11 = fy * fx                 * vy1 * vx1;
            int cy0 = min(max(y0, 0), HD - 1), cy1 = min(max(y1, 0), HD - 1);
            int cx0 = min(max(x0, 0), WD - 1), cx1 = min(max(x1, 0), WD - 1);
            g_mwgt[base + k * WD] = make_float4(w00, w01, w10, w11);
            g_midx[base + k * WD] = make_int4((cy0 * WD + cx0) * CIN,
                                              (cy0 * WD + cx1) * CIN,
                                              (cy1 * WD + cx0) * CIN,
                                              (cy1 * WD + cx1) * CIN);
        }
    }
}

// ---------------- main: warp-specialized sample + GEMM ----------------------
// grid (HD, BD) = one row of 128 px per CTA; 384 threads:
//   threads 0..255   = producers: gather S[chunk] + stage W[chunk]
//   threads 256..383 = consumers: 72-row GEMM, thread tile 8px x 8out
// Double-buffered S and W; one __syncthreads per chunk interval.
#define SROW  132                      // S row stride (floats): conflict-free
#define WROW  96                       // W row stride: 8 groups of (8 + 4 pad)
#define SBUF  (72 * SROW)              // 9504 floats
#define WBUF  (72 * WROW)              // 6912 floats
#define SMEM_MAIN ((2 * SBUF + 2 * WBUF) * 4)   // 131,328 B -> 1 CTA/SM

__global__ __launch_bounds__(384, 1)
void k_main(float* __restrict__ out) {
    extern __shared__ float smem[];
    float* Sb0 = smem;
    float* Sb1 = smem + SBUF;
    float* Wb0 = smem + 2 * SBUF;
    float* Wb1 = smem + 2 * SBUF + WBUF;

    int h = blockIdx.x, b = blockIdx.y, t = threadIdx.x;

    const float* xb = g_xhwc + (size_t)b * HW * CIN;
    int mbase = (b * HD + h) * KK * WD;
    const float4* mw = g_mwgt + mbase;
    const int4*   mi = g_midx + mbase;

    // consumer state (allocated in all threads; used by consumers only)
    ull acc[4][8];
    #pragma unroll
    for (int i = 0; i < 4; ++i)
        #pragma unroll
        for (int o = 0; o < 8; ++o) acc[i][o] = 0ULL;

    bool producer = (t < 256);
    int c2 = t & 3, g = t >> 2;            // producer map: 4 ch-pairs x 64 groups
    int tc = t - 256;
    int og = tc & 7, pg = tc >> 3;         // consumer map: 8 out x 16 px-groups

    for (int cc = 0; cc < 9; ++cc) {
        if (producer) {
            if (cc < 8) {
                float* S = (cc & 1) ? Sb1 : Sb0;
                float* W = (cc & 1) ? Wb1 : Wb0;
                // stage W for this chunk (coalesced, L2-resident)
                const float* wsrc = g_wd1 + cc * 72 * 64;
                #pragma unroll
                for (int i = 0; i < 18; ++i) {
                    int id = t + i * 256;
                    int row = id >> 6, o = id & 63;
                    W[row * WROW + (o >> 3) * 12 + (o & 7)] = wsrc[id];
                }
                // gather S: 2 channels per lane per tap-corner
                const float* xc = xb + cc * 8 + c2 * 2;
                #pragma unroll 2
                for (int it = 0; it < 18; ++it) {
                    int pi = it * 64 + g;              // k*128 + p
                    float4 wg = mw[pi];
                    int4   ii = mi[pi];
                    ull v0 = *(const ull*)(xc + ii.x);
                    ull v1 = *(const ull*)(xc + ii.y);
                    ull v2 = *(const ull*)(xc + ii.z);
                    ull v3 = *(const ull*)(xc + ii.w);
                    ull s = 0ULL;
                    fma2(s, v0, pack2(wg.x, wg.x));
                    fma2(s, v1, pack2(wg.y, wg.y));
                    fma2(s, v2, pack2(wg.z, wg.z));
                    fma2(s, v3, pack2(wg.w, wg.w));
                    float2 sv = unpack2(s);
                    int k = pi >> 7, p = pi & 127;
                    float* sp = S + ((c2 * 2) * KK + k) * SROW + p;
                    sp[0]        = sv.x;
                    sp[9 * SROW] = sv.y;
                }
            }
        } else {
            if (cc > 0) {
                const float* S = ((cc - 1) & 1) ? Sb1 : Sb0;
                const float* W = ((cc - 1) & 1) ? Wb1 : Wb0;
                const float* srow = S + pg * 8;
                const float* wrow = W + og * 12;
                #pragma unroll 2
                for (int row = 0; row < 72; ++row) {
                    ulonglong2 s01 = *(const ulonglong2*)(srow + row * SROW);
                    ulonglong2 s23 = *(const ulonglong2*)(srow + row * SROW + 4);
                    float4 wa = *(const float4*)(wrow + row * WROW);
                    float4 wb = *(const float4*)(wrow + row * WROW + 4);
                    ull w0 = pack2(wa.x, wa.x), w1 = pack2(wa.y, wa.y);
                    ull w2 = pack2(wa.z, wa.z), w3 = pack2(wa.w, wa.w);
                    ull w4 = pack2(wb.x, wb.x), w5 = pack2(wb.y, wb.y);
                    ull w6 = pack2(wb.z, wb.z), w7 = pack2(wb.w, wb.w);
                    fma2(acc[0][0], s01.x, w0); fma2(acc[1][0], s01.y, w0);
                    fma2(acc[2][0], s23.x, w0); fma2(acc[3][0], s23.y, w0);
                    fma2(acc[0][1], s01.x, w1); fma2(acc[1][1], s01.y, w1);
                    fma2(acc[2][1], s23.x, w1); fma2(acc[3][1], s23.y, w1);
                    fma2(acc[0][2], s01.x, w2); fma2(acc[1][2], s01.y, w2);
                    fma2(acc[2][2], s23.x, w2); fma2(acc[3][2], s23.y, w2);
                    fma2(acc[0][3], s01.x, w3); fma2(acc[1][3], s01.y, w3);
                    fma2(acc[2][3], s23.x, w3); fma2(acc[3][3], s23.y, w3);
                    fma2(acc[0][4], s01.x, w4); fma2(acc[1][4], s01.y, w4);
                    fma2(acc[2][4], s23.x, w4); fma2(acc[3][4], s23.y, w4);
                    fma2(acc[0][5], s01.x, w5); fma2(acc[1][5], s01.y, w5);
                    fma2(acc[2][5], s23.x, w5); fma2(acc[3][5], s23.y, w5);
                    fma2(acc[0][6], s01.x, w6); fma2(acc[1][6], s01.y, w6);
                    fma2(acc[2][6], s23.x, w6); fma2(acc[3][6], s23.y, w6);
                    fma2(acc[0][7], s01.x, w7); fma2(acc[1][7], s01.y, w7);
                    fma2(acc[2][7], s23.x, w7); fma2(acc[3][7], s23.y, w7);
                }
            }
        }
        __syncthreads();
    }

    // ---- consumer epilogue: out[b][og*8+o][h][pg*8 .. +7] -------------------
    if (!producer) {
        float* op = out + (((size_t)(b * COUT + og * 8) * HD + h) * WD) + pg * 8;
        #pragma unroll
        for (int o = 0; o < 8; ++o) {
            float2 a0 = unpack2(acc[0][o]);
            float2 a1 = unpack2(acc[1][o]);
            float2 a2 = unpack2(acc[2][o]);
            float2 a3 = unpack2(acc[3][o]);
            *(float4*)(op + (size_t)o * HW)     = make_float4(a0.x, a0.y, a1.x, a1.y);
            *(float4*)(op + (size_t)o * HW + 4) = make_float4(a2.x, a2.y, a3.x, a3.y);
        }
    }
}

// ------------------------------- launch -------------------------------------
extern "C" void kernel_launch(void* const* d_in, const int* in_sizes, int n_in,
                              void* d_out, int out_size) {
    const float* x     = (const float*)d_in[0];
    const float* w_off = (const float*)d_in[1];
    const float* b_off = (const float*)d_in[2];
    const float* w_def = (const float*)d_in[3];
    float* out = (float*)d_out;

    (void)cudaFuncSetAttribute(k_main, cudaFuncAttributeMaxDynamicSharedMemorySize, SMEM_MAIN);

    k_tr      <<<dim3(HW / 64, BD), 256>>>(x);
    k_prep_w  <<<(CIN * KK * COUT + 255) / 256, 256>>>(w_def);
    k_prep_off<<<(576 * 9 + 255) / 256, 256>>>(w_off);
    k_off     <<<dim3(HD / 2, BD), 128>>>(x, b_off);
    k_main    <<<dim3(HD, BD), 384, SMEM_MAIN>>>(out);
}

// round 13
// speedup vs baseline: 1.3429x; 1.0697x over previous
#include <cuda_runtime.h>
#include <cstdint>

#define CIN   64
#define COUT  64
#define HD    128
#define WD    128
#define BD    4
#define KK    9
#define HW    (HD*WD)

// ------------------------- scratch (device globals) -------------------------
__device__ float  g_xhwc[BD*HW*CIN];          // x in NHWC (16 MB)
__device__ float  g_wdk [KK*CIN*COUT];        // w_def re-packed [k][c][o]
__device__ float4 g_mwgt[BD*HD*KK*WD];        // bilinear weights (validity folded)
__device__ int4   g_midx[BD*HD*KK*WD];        // tap indices, pre-multiplied by 64
__device__ unsigned long long g_woffp[576*9]; // w_off prepacked [tap*64+c][j] {wy,wx}

typedef unsigned long long ull;

__device__ __forceinline__ void fma2(ull &acc, ull a, ull b) {
    asm("fma.rn.f32x2 %0, %1, %2, %0;" : "+l"(acc) : "l"(a), "l"(b));
}
__device__ __forceinline__ ull pack2(float a, float b) {
    ull r; asm("mov.b64 %0, {%1, %2};" : "=l"(r) : "f"(a), "f"(b)); return r;
}
__device__ __forceinline__ float2 unpack2(ull v) {
    float2 r; asm("mov.b64 {%0, %1}, %2;" : "=f"(r.x), "=f"(r.y) : "l"(v)); return r;
}

// ------------------------- kernel: NCHW -> NHWC -----------------------------
__global__ __launch_bounds__(256)
void k_tr(const float* __restrict__ x) {
    __shared__ float tile[64][65];
    int b = blockIdx.y, hw0 = blockIdx.x * 64, t = threadIdx.x;
    const float* xb = x + (size_t)b * CIN * HW;
    #pragma unroll
    for (int it = 0; it < 16; ++it) {
        int id = t + it * 256;
        int c = id >> 6, i = id & 63;
        tile[c][i] = xb[c * HW + hw0 + i];
    }
    __syncthreads();
    float* ob = g_xhwc + (size_t)b * HW * CIN + (size_t)hw0 * CIN;
    #pragma unroll
    for (int it = 0; it < 16; ++it) {
        int id = t + it * 256;
        int i = id >> 6, c = id & 63;
        ob[id] = tile[c][i];
    }
}

// --------------------- prepack w_def as [k][c][o] ---------------------------
__global__ void k_prep_w(const float* __restrict__ w_def) {
    int id = blockIdx.x * 256 + threadIdx.x;      // 0 .. 36863
    if (id >= KK * CIN * COUT) return;
    int o = id & 63;
    int c = (id >> 6) & 63;
    int k = id >> 12;
    g_wdk[id] = w_def[(o * CIN + c) * KK + k];
}

// --------------------- prepack w_off (paired {wy,wx}) -----------------------
__global__ void k_prep_off(const float* __restrict__ w_off) {
    int id = blockIdx.x * 256 + threadIdx.x;      // 0 .. 5183
    if (id >= 576 * 9) return;
    int grp = id / 9, j = id - grp * 9;
    int tap = grp >> 6, c = grp & 63;
    float wa = w_off[((2 * j    ) * CIN + c) * KK + tap];
    float wb = w_off[((2 * j + 1) * CIN + c) * KK + tap];
    g_woffp[id] = pack2(wa, wb);
}

// ------------- kernel: offset conv + bilinear metadata ----------------------
// grid (HD/4, BD), 256 threads: two 128-thread halves, each owns 2 output rows
__global__ __launch_bounds__(256)
void k_off(const float* __restrict__ x, const float* __restrict__ b_off) {
    __shared__ ull woffp[576 * 10];   // [tap*64+c][j], padded to 10 (16B align)
    int b = blockIdx.y, t = threadIdx.x;
    int h0 = blockIdx.x * 4 + ((t >> 7) << 1);   // rows h0, h0+1 for this half
    int tw = t & 127;

    for (int id = t; id < 576 * 9; id += 256) {
        int grp = id / 9, j = id - grp * 9;
        woffp[grp * 10 + j] = g_woffp[id];
    }
    __syncthreads();

    ull acc0[9], acc1[9];
    #pragma unroll
    for (int j = 0; j < 9; ++j) { acc0[j] = 0ULL; acc1[j] = 0ULL; }

    const float* xb = x + (size_t)b * CIN * HW;
    #pragma unroll
    for (int tap = 0; tap < 9; ++tap) {
        int ty = tap / 3, tx = tap % 3;
        int sy0 = h0 - 1 + ty;
        int sy1 = sy0 + 1;
        bool v0 = (sy0 >= 0) && (sy0 < HD);
        bool v1 = (sy1 >= 0) && (sy1 < HD);
        if (!v0 && !v1) continue;
        int wx = tw - 1 + tx;
        bool vx = (wx >= 0) && (wx < WD);
        const float* xr0 = xb + sy0 * WD + wx;
        const float* xr1 = xr0 + WD;
        const ull* wp0 = woffp + tap * 64 * 10;
        for (int c = 0; c < 64; ++c) {
            float xv0 = (v0 && vx) ? xr0[c * HW] : 0.f;
            float xv1 = (v1 && vx) ? xr1[c * HW] : 0.f;
            ull xp0 = pack2(xv0, xv0);
            ull xp1 = pack2(xv1, xv1);
            const ull* wp = wp0 + c * 10;
            ulonglong2 q0 = *(const ulonglong2*)(wp);
            ulonglong2 q1 = *(const ulonglong2*)(wp + 2);
            ulonglong2 q2 = *(const ulonglong2*)(wp + 4);
            ulonglong2 q3 = *(const ulonglong2*)(wp + 6);
            ull        q8 = wp[8];
            fma2(acc0[0], xp0, q0.x); fma2(acc1[0], xp1, q0.x);
            fma2(acc0[1], xp0, q0.y); fma2(acc1[1], xp1, q0.y);
            fma2(acc0[2], xp0, q1.x); fma2(acc1[2], xp1, q1.x);
            fma2(acc0[3], xp0, q1.y); fma2(acc1[3], xp1, q1.y);
            fma2(acc0[4], xp0, q2.x); fma2(acc1[4], xp1, q2.x);
            fma2(acc0[5], xp0, q2.y); fma2(acc1[5], xp1, q2.y);
            fma2(acc0[6], xp0, q3.x); fma2(acc1[6], xp1, q3.x);
            fma2(acc0[7], xp0, q3.y); fma2(acc1[7], xp1, q3.y);
            fma2(acc0[8], xp0, q8);   fma2(acc1[8], xp1, q8);
        }
    }

    #pragma unroll
    for (int r = 0; r < 2; ++r) {
        int h = h0 + r;
        int base = ((b * HD + h) * KK) * WD + tw;
        #pragma unroll
        for (int k = 0; k < 9; ++k) {
            float2 o2 = unpack2(r == 0 ? acc0[k] : acc1[k]);
            float dy  = o2.x + b_off[2 * k];
            float dxo = o2.y + b_off[2 * k + 1];
            float py = (float)(h - 1 + k / 3) + dy;
            float px = (float)(tw - 1 + k % 3) + dxo;
            float y0f = floorf(py), x0f = floorf(px);
            float fy = py - y0f, fx = px - x0f;
            int y0 = (int)y0f, x0 = (int)x0f;
            int y1 = y0 + 1, x1 = x0 + 1;
            float vy0 = (y0 >= 0 && y0 < HD) ? 1.f : 0.f;
            float vy1 = (y1 >= 0 && y1 < HD) ? 1.f : 0.f;
            float vx0 = (x0 >= 0 && x0 < WD) ? 1.f : 0.f;
            float vx1 = (x1 >= 0 && x1 < WD) ? 1.f : 0.f;
            float w00 = (1.f - fy) * (1.f - fx) * vy0 * vx0;
            float w01 = (1.f - fy) * fx         * vy0 * vx1;
            float w10 = fy * (1.f - fx)         * vy1 * vx0;
            float w11 = fy * fx                 * vy1 * vx1;
            int cy0 = min(max(y0, 0), HD - 1), cy1 = min(max(y1, 0), HD - 1);
            int cx0 = min(max(x0, 0), WD - 1), cx1 = min(max(x1, 0), WD - 1);
            g_mwgt[base + k * WD] = make_float4(w00, w01, w10, w11);
            g_midx[base + k * WD] = make_int4((cy0 * WD + cx0) * CIN,
                                              (cy0 * WD + cx1) * CIN,
                                              (cy1 * WD + cx0) * CIN,
                                              (cy1 * WD + cx1) * CIN);
        }
    }
}

// ---------------- main: tap-chunked warp-specialized sample + GEMM ----------
// grid (HD, BD) = one row of 128 px per CTA; 512 threads:
//   t 0..255   producers: per tap, gather all 64 channels (256B lines, 1x)
//   t 256..511 consumers: 64-row GEMM per tap, thread tile 4px x 8out
// S[c][p] rows swizzled in 4-px blocks: block q stored at q' = (q + c/4) & 31.
#define SROW  132
#define WROW  96
#define SBUF  (64 * SROW)              // 8448 floats
#define WBUF  (64 * WROW)              // 6144 floats
#define SMEM_MAIN ((2 * SBUF + 2 * WBUF) * 4)   // 116,736 B -> 1 CTA/SM

__global__ __launch_bounds__(512, 1)
void k_main(float* __restrict__ out) {
    extern __shared__ float smem[];
    float* Sb0 = smem;
    float* Sb1 = smem + SBUF;
    float* Wb0 = smem + 2 * SBUF;
    float* Wb1 = smem + 2 * SBUF + WBUF;

    int h = blockIdx.x, b = blockIdx.y, t = threadIdx.x;

    const float* xb = g_xhwc + (size_t)b * HW * CIN;
    int mbase = (b * HD + h) * KK * WD;
    const float4* mw = g_mwgt + mbase;
    const int4*   mi = g_midx + mbase;

    ull acc[2][8];
    #pragma unroll
    for (int i = 0; i < 2; ++i)
        #pragma unroll
        for (int o = 0; o < 8; ++o) acc[i][o] = 0ULL;

    bool producer = (t < 256);
    int c16 = t & 15, pgrp = t >> 4;        // producer: 16 ch-quads x 16 px-groups
    int tc = t - 256;
    int og = tc & 7, pg = tc >> 3;          // consumer: 8 out-groups x 32 px-blocks

    for (int cc = 0; cc < 10; ++cc) {
        if (producer) {
            if (cc < 9) {
                float* S = (cc & 1) ? Sb1 : Sb0;
                float* W = (cc & 1) ? Wb1 : Wb0;
                // stage W[k=cc] (contiguous 16 KB, L2-resident)
                const float* wsrc = g_wdk + cc * CIN * COUT;
                #pragma unroll
                for (int i = 0; i < 16; ++i) {
                    int id = t + i * 256;
                    int c = id >> 6, o = id & 63;
                    W[c * WROW + (o >> 3) * 12 + (o & 7)] = wsrc[id];
                }
                // gather: all 64 channels per corner, one pass
                const float4* mwc = mw + cc * WD;
                const int4*   mic = mi + cc * WD;
                const float*  xq  = xb + c16 * 4;
                #pragma unroll 2
                for (int j = 0; j < 8; ++j) {
                    int p = pgrp * 8 + j;
                    float4 wg = mwc[p];
                    int4   ii = mic[p];
                    ulonglong2 v0 = *(const ulonglong2*)(xq + ii.x);
                    ulonglong2 v1 = *(const ulonglong2*)(xq + ii.y);
                    ulonglong2 v2 = *(const ulonglong2*)(xq + ii.z);
                    ulonglong2 v3 = *(const ulonglong2*)(xq + ii.w);
                    ull wA = pack2(wg.x, wg.x), wB = pack2(wg.y, wg.y);
                    ull wC = pack2(wg.z, wg.z), wD = pack2(wg.w, wg.w);
                    ull slo = 0ULL, shi = 0ULL;
                    fma2(slo, v0.x, wA); fma2(shi, v0.y, wA);
                    fma2(slo, v1.x, wB); fma2(shi, v1.y, wB);
                    fma2(slo, v2.x, wC); fma2(shi, v2.y, wC);
                    fma2(slo, v3.x, wD); fma2(shi, v3.y, wD);
                    float2 lo = unpack2(slo), hi = unpack2(shi);
                    int q = p >> 2, pm = p & 3;
                    int qp = ((q + c16) & 31) << 2;
                    float* s0 = S + (c16 * 4) * SROW + qp + pm;
                    s0[0]        = lo.x;
                    s0[SROW]     = lo.y;
                    s0[2 * SROW] = hi.x;
                    s0[3 * SROW] = hi.y;
                }
            }
        } else {
            if (cc > 0) {
                const float* S = ((cc - 1) & 1) ? Sb1 : Sb0;
                const float* W = ((cc - 1) & 1) ? Wb1 : Wb0;
                const float* wrow = W + og * 12;
                #pragma unroll 4
                for (int c = 0; c < 64; ++c) {
                    const float* sp = S + c * SROW + (((pg + (c >> 2)) & 31) << 2);
                    ulonglong2 s01 = *(const ulonglong2*)sp;
                    float4 wa = *(const float4*)(wrow + c * WROW);
                    float4 wb = *(const float4*)(wrow + c * WROW + 4);
                    ull w0 = pack2(wa.x, wa.x), w1 = pack2(wa.y, wa.y);
                    ull w2 = pack2(wa.z, wa.z), w3 = pack2(wa.w, wa.w);
                    ull w4 = pack2(wb.x, wb.x), w5 = pack2(wb.y, wb.y);
                    ull w6 = pack2(wb.z, wb.z), w7 = pack2(wb.w, wb.w);
                    fma2(acc[0][0], s01.x, w0); fma2(acc[1][0], s01.y, w0);
                    fma2(acc[0][1], s01.x, w1); fma2(acc[1][1], s01.y, w1);
                    fma2(acc[0][2], s01.x, w2); fma2(acc[1][2], s01.y, w2);
                    fma2(acc[0][3], s01.x, w3); fma2(acc[1][3], s01.y, w3);
                    fma2(acc[0][4], s01.x, w4); fma2(acc[1][4], s01.y, w4);
                    fma2(acc[0][5], s01.x, w5); fma2(acc[1][5], s01.y, w5);
                    fma2(acc[0][6], s01.x, w6); fma2(acc[1][6], s01.y, w6);
                    fma2(acc[0][7], s01.x, w7); fma2(acc[1][7], s01.y, w7);
                }
            }
        }
        __syncthreads();
    }

    // ---- consumer epilogue: out[b][og*8+o][h][pg*4 .. +3] -------------------
    if (!producer) {
        float* op = out + (((size_t)(b * COUT + og * 8) * HD + h) * WD) + pg * 4;
        #pragma unroll
        for (int o = 0; o < 8; ++o) {
            float2 a0 = unpack2(acc[0][o]);
            float2 a1 = unpack2(acc[1][o]);
            *(float4*)(op + (size_t)o * HW) = make_float4(a0.x, a0.y, a1.x, a1.y);
        }
    }
}

// ------------------------------- launch -------------------------------------
extern "C" void kernel_launch(void* const* d_in, const int* in_sizes, int n_in,
                              void* d_out, int out_size) {
    const float* x     = (const float*)d_in[0];
    const float* w_off = (const float*)d_in[1];
    const float* b_off = (const float*)d_in[2];
    const float* w_def = (const float*)d_in[3];
    float* out = (float*)d_out;

    (void)cudaFuncSetAttribute(k_main, cudaFuncAttributeMaxDynamicSharedMemorySize, SMEM_MAIN);

    k_tr      <<<dim3(HW / 64, BD), 256>>>(x);
    k_prep_w  <<<(KK * CIN * COUT + 255) / 256, 256>>>(w_def);
    k_prep_off<<<(576 * 9 + 255) / 256, 256>>>(w_off);
    k_off     <<<dim3(HD / 4, BD), 256>>>(x, b_off);
    k_main    <<<dim3(HD, BD), 512, SMEM_MAIN>>>(out);
}

// round 15
// speedup vs baseline: 1.3830x; 1.0299x over previous
#include <cuda_runtime.h>
#include <cstdint>

#define CIN   64
#define COUT  64
#define HD    128
#define WD    128
#define BD    4
#define KK    9
#define HW    (HD*WD)

// ------------------------- scratch (device globals) -------------------------
__device__ float  g_xhwc[BD*HW*CIN];          // x in NHWC (16 MB)
__device__ float  g_wdk [KK*CIN*COUT];        // w_def re-packed [k][c][o]
__device__ unsigned long long g_woffp[576*9]; // w_off prepacked [tap*64+c][j] {wy,wx}

typedef unsigned long long ull;

__device__ __forceinline__ void fma2(ull &acc, ull a, ull b) {
    asm("fma.rn.f32x2 %0, %1, %2, %0;" : "+l"(acc) : "l"(a), "l"(b));
}
__device__ __forceinline__ void add2(ull &acc, ull a) {
    asm("add.rn.f32x2 %0, %0, %1;" : "+l"(acc) : "l"(a));
}
__device__ __forceinline__ ull pack2(float a, float b) {
    ull r; asm("mov.b64 %0, {%1, %2};" : "=l"(r) : "f"(a), "f"(b)); return r;
}
__device__ __forceinline__ float2 unpack2(ull v) {
    float2 r; asm("mov.b64 {%0, %1}, %2;" : "=f"(r.x), "=f"(r.y) : "l"(v)); return r;
}

// ------------------------- kernel: NCHW -> NHWC -----------------------------
__global__ __launch_bounds__(256)
void k_tr(const float* __restrict__ x) {
    __shared__ float tile[64][65];
    int b = blockIdx.y, hw0 = blockIdx.x * 64, t = threadIdx.x;
    const float* xb = x + (size_t)b * CIN * HW;
    #pragma unroll
    for (int it = 0; it < 16; ++it) {
        int id = t + it * 256;
        int c = id >> 6, i = id & 63;
        tile[c][i] = xb[c * HW + hw0 + i];
    }
    __syncthreads();
    float* ob = g_xhwc + (size_t)b * HW * CIN + (size_t)hw0 * CIN;
    #pragma unroll
    for (int it = 0; it < 16; ++it) {
        int id = t + it * 256;
        int i = id >> 6, c = id & 63;
        ob[id] = tile[c][i];
    }
}

// --------------------- prepack w_def as [k][c][o] ---------------------------
__global__ void k_prep_w(const float* __restrict__ w_def) {
    int id = blockIdx.x * 256 + threadIdx.x;      // 0 .. 36863
    if (id >= KK * CIN * COUT) return;
    int o = id & 63;
    int c = (id >> 6) & 63;
    int k = id >> 12;
    g_wdk[id] = w_def[(o * CIN + c) * KK + k];
}

// --------------------- prepack w_off (paired {wy,wx}) -----------------------
__global__ void k_prep_off(const float* __restrict__ w_off) {
    int id = blockIdx.x * 256 + threadIdx.x;      // 0 .. 5183
    if (id >= 576 * 9) return;
    int grp = id / 9, j = id - grp * 9;
    int tap = grp >> 6, c = grp & 63;
    float wa = w_off[((2 * j    ) * CIN + c) * KK + tap];
    float wb = w_off[((2 * j + 1) * CIN + c) * KK + tap];
    g_woffp[id] = pack2(wa, wb);
}

// ------------- fused: offset conv + metadata + sample + GEMM ---------------
// grid (HD, BD) = one (b, h) row of 128 px per CTA, 384 threads.
// Phase A (t<256): offset conv, 128 px x 2 channel-halves; smem-reduce;
//                  t<128 emit bilinear metadata into smem (no global trip).
// Phase B: t<256 producers (per-tap gather, 64 channels/corner in one pass),
//          t>=256 consumers (128 thr, 8px x 8out register tile).
#define SROW  132
#define WROW  96
#define SBUF  (64 * SROW)              // 8448 floats
#define WBUF  (64 * WROW)              // 6144 floats
// smem float offsets
#define OFF_MWGT  0                    // float4[9*128]  = 4608 floats
#define OFF_MIDX  4608                 // int4[9*128]    = 4608 slots
#define OFF_S0    9216
#define OFF_S1    (OFF_S0 + SBUF)
#define OFF_W0    (OFF_S0 + 2*SBUF)    // 26112
#define OFF_W1    (OFF_W0 + WBUF)
#define OFF_WOFFP OFF_S0               // alias: ull[5760] = 11520 floats < 2*SBUF
#define OFF_RED   OFF_W0               // alias: ull[128*9] = 2304 floats < WBUF
#define SMEM_FUSED ((OFF_W1 + WBUF) * 4)   // 153,600 B -> 1 CTA/SM

__global__ __launch_bounds__(384, 1)
void k_fused(const float* __restrict__ x, const float* __restrict__ b_off,
             float* __restrict__ out) {
    extern __shared__ float smem[];
    float4* mwgt_s = (float4*)(smem + OFF_MWGT);
    int4*   midx_s = (int4*)  (smem + OFF_MIDX);
    ull*    woffp  = (ull*)   (smem + OFF_WOFFP);
    ull*    red    = (ull*)   (smem + OFF_RED);
    float*  Sb0 = smem + OFF_S0;
    float*  Sb1 = smem + OFF_S1;
    float*  Wb0 = smem + OFF_W0;
    float*  Wb1 = smem + OFF_W1;

    int h = blockIdx.x, b = blockIdx.y, t = threadIdx.x;

    // ---- load packed offset-conv weights into smem (aliases S bufs) --------
    for (int id = t; id < 576 * 9; id += 384) {
        int grp = id / 9, j = id - grp * 9;
        woffp[grp * 10 + j] = g_woffp[id];
    }
    __syncthreads();

    // ======================= Phase A: offset conv ===========================
    ull oacc[9];
    #pragma unroll
    for (int j = 0; j < 9; ++j) oacc[j] = 0ULL;

    if (t < 256) {
        int px = t & 127, half = t >> 7;
        const float* xb = x + (size_t)b * CIN * HW + (size_t)(half * 32) * HW;
        #pragma unroll
        for (int tap = 0; tap < 9; ++tap) {
            int hy = h + tap / 3 - 1;
            if (hy < 0 || hy >= HD) continue;
            int wx = px + tap % 3 - 1;
            bool vx = (wx >= 0) && (wx < WD);
            const float* xr = xb + hy * WD + wx;
            const ull* wp0 = woffp + tap * 640 + half * 320;
            for (int c = 0; c < 32; ++c) {
                float xv = vx ? xr[c * HW] : 0.f;
                ull xp = pack2(xv, xv);
                const ull* wp = wp0 + c * 10;
                ulonglong2 q0 = *(const ulonglong2*)(wp);
                ulonglong2 q1 = *(const ulonglong2*)(wp + 2);
                ulonglong2 q2 = *(const ulonglong2*)(wp + 4);
                ulonglong2 q3 = *(const ulonglong2*)(wp + 6);
                ull        q8 = wp[8];
                fma2(oacc[0], xp, q0.x); fma2(oacc[1], xp, q0.y);
                fma2(oacc[2], xp, q1.x); fma2(oacc[3], xp, q1.y);
                fma2(oacc[4], xp, q2.x); fma2(oacc[5], xp, q2.y);
                fma2(oacc[6], xp, q3.x); fma2(oacc[7], xp, q3.y);
                fma2(oacc[8], xp, q8);
            }
        }
        if (half) {
            #pragma unroll
            for (int j = 0; j < 9; ++j) red[px * 9 + j] = oacc[j];
        }
    }
    __syncthreads();

    if (t < 128) {
        int px = t;
        #pragma unroll
        for (int k = 0; k < 9; ++k) {
            add2(oacc[k], red[px * 9 + k]);
            float2 o2 = unpack2(oacc[k]);
            float dy  = o2.x + b_off[2 * k];
            float dxo = o2.y + b_off[2 * k + 1];
            float py = (float)(h - 1 + k / 3) + dy;
            float pxx = (float)(px - 1 + k % 3) + dxo;
            float y0f = floorf(py), x0f = floorf(pxx);
            float fy = py - y0f, fx = pxx - x0f;
            int y0 = (int)y0f, x0 = (int)x0f;
            int y1 = y0 + 1, x1 = x0 + 1;
            float vy0 = (y0 >= 0 && y0 < HD) ? 1.f : 0.f;
            float vy1 = (y1 >= 0 && y1 < HD) ? 1.f : 0.f;
            float vx0 = (x0 >= 0 && x0 < WD) ? 1.f : 0.f;
            float vx1 = (x1 >= 0 && x1 < WD) ? 1.f : 0.f;
            float w00 = (1.f - fy) * (1.f - fx) * vy0 * vx0;
            float w01 = (1.f - fy) * fx         * vy0 * vx1;
            float w10 = fy * (1.f - fx)         * vy1 * vx0;
            float w11 = fy * fx                 * vy1 * vx1;
            int cy0 = min(max(y0, 0), HD - 1), cy1 = min(max(y1, 0), HD - 1);
            int cx0 = min(max(x0, 0), WD - 1), cx1 = min(max(x1, 0), WD - 1);
            mwgt_s[k * 128 + px] = make_float4(w00, w01, w10, w11);
            midx_s[k * 128 + px] = make_int4((cy0 * WD + cx0) * CIN,
                                             (cy0 * WD + cx1) * CIN,
                                             (cy1 * WD + cx0) * CIN,
                                             (cy1 * WD + cx1) * CIN);
        }
    }
    __syncthreads();   // metadata ready; woffp/red regions now reusable

    // ======================= Phase B: gather + GEMM =========================
    const float* xbh = g_xhwc + (size_t)b * HW * CIN;

    ull acc[4][8];
    #pragma unroll
    for (int i = 0; i < 4; ++i)
        #pragma unroll
        for (int o = 0; o < 8; ++o) acc[i][o] = 0ULL;

    bool producer = (t < 256);
    int c16 = t & 15, pgrp = t >> 4;        // producer: 16 ch-quads x 16 px-grps
    int tc = t - 256;
    int og = tc & 7, pg = tc >> 3;          // consumer: 8 out x 16 px-groups(8px)

    for (int cc = 0; cc < 10; ++cc) {
        if (producer) {
            if (cc < 9) {
                float* S = (cc & 1) ? Sb1 : Sb0;
                float* W = (cc & 1) ? Wb1 : Wb0;
                // stage W[k=cc] (contiguous 16 KB, L2-resident)
                const float* wsrc = g_wdk + cc * CIN * COUT;
                #pragma unroll
                for (int i = 0; i < 16; ++i) {
                    int id = t + i * 256;
                    int c = id >> 6, o = id & 63;
                    W[c * WROW + (o >> 3) * 12 + (o & 7)] = wsrc[id];
                }
                // gather: all 64 channels per corner, one pass
                const float4* mwc = mwgt_s + cc * 128;
                const int4*   mic = midx_s + cc * 128;
                const float*  xq  = xbh + c16 * 4;
                #pragma unroll 2
                for (int j = 0; j < 8; ++j) {
                    int p = pgrp * 8 + j;
                    float4 wg = mwc[p];
                    int4   ii = mic[p];
                    ulonglong2 v0 = *(const ulonglong2*)(xq + ii.x);
                    ulonglong2 v1 = *(const ulonglong2*)(xq + ii.y);
                    ulonglong2 v2 = *(const ulonglong2*)(xq + ii.z);
                    ulonglong2 v3 = *(const ulonglong2*)(xq + ii.w);
                    ull wA = pack2(wg.x, wg.x), wB = pack2(wg.y, wg.y);
                    ull wC = pack2(wg.z, wg.z), wD = pack2(wg.w, wg.w);
                    ull slo = 0ULL, shi = 0ULL;
                    fma2(slo, v0.x, wA); fma2(shi, v0.y, wA);
                    fma2(slo, v1.x, wB); fma2(shi, v1.y, wB);
                    fma2(slo, v2.x, wC); fma2(shi, v2.y, wC);
                    fma2(slo, v3.x, wD); fma2(shi, v3.y, wD);
                    float2 lo = unpack2(slo), hi = unpack2(shi);
                    int q = p >> 2, pm = p & 3;
                    int qp = ((q + c16) & 31) << 2;
                    float* s0 = S + (c16 * 4) * SROW + qp + pm;
                    s0[0]        = lo.x;
                    s0[SROW]     = lo.y;
                    s0[2 * SROW] = hi.x;
                    s0[3 * SROW] = hi.y;
                }
            }
        } else {
            if (cc > 0) {
                const float* S = ((cc - 1) & 1) ? Sb1 : Sb0;
                const float* W = ((cc - 1) & 1) ? Wb1 : Wb0;
                const float* wrow = W + og * 12;
                #pragma unroll 4
                for (int c = 0; c < 64; ++c) {
                    const float* Sc = S + c * SROW;
                    int c4 = c >> 2;
                    int blk0 = ((2 * pg + c4) & 31) << 2;
                    int blk1 = ((2 * pg + 1 + c4) & 31) << 2;
                    ulonglong2 s01 = *(const ulonglong2*)(Sc + blk0);
                    ulonglong2 s23 = *(const ulonglong2*)(Sc + blk1);
                    float4 wa = *(const float4*)(wrow + c * WROW);
                    float4 wb = *(const float4*)(wrow + c * WROW + 4);
                    ull w0 = pack2(wa.x, wa.x), w1 = pack2(wa.y, wa.y);
                    ull w2 = pack2(wa.z, wa.z), w3 = pack2(wa.w, wa.w);
                    ull w4 = pack2(wb.x, wb.x), w5 = pack2(wb.y, wb.y);
                    ull w6 = pack2(wb.z, wb.z), w7 = pack2(wb.w, wb.w);
                    fma2(acc[0][0], s01.x, w0); fma2(acc[1][0], s01.y, w0);
                    fma2(acc[2][0], s23.x, w0); fma2(acc[3][0], s23.y, w0);
                    fma2(acc[0][1], s01.x, w1); fma2(acc[1][1], s01.y, w1);
                    fma2(acc[2][1], s23.x, w1); fma2(acc[3][1], s23.y, w1);
                    fma2(acc[0][2], s01.x, w2); fma2(acc[1][2], s01.y, w2);
                    fma2(acc[2][2], s23.x, w2); fma2(acc[3][2], s23.y, w2);
                    fma2(acc[0][3], s01.x, w3); fma2(acc[1][3], s01.y, w3);
                    fma2(acc[2][3], s23.x, w3); fma2(acc[3][3], s23.y, w3);
                    fma2(acc[0][4], s01.x, w4); fma2(acc[1][4], s01.y, w4);
                    fma2(acc[2][4], s23.x, w4); fma2(acc[3][4], s23.y, w4);
                    fma2(acc[0][5], s01.x, w5); fma2(acc[1][5], s01.y, w5);
                    fma2(acc[2][5], s23.x, w5); fma2(acc[3][5], s23.y, w5);
                    fma2(acc[0][6], s01.x, w6); fma2(acc[1][6], s01.y, w6);
                    fma2(acc[2][6], s23.x, w6); fma2(acc[3][6], s23.y, w6);
                    fma2(acc[0][7], s01.x, w7); fma2(acc[1][7], s01.y, w7);
                    fma2(acc[2][7], s23.x, w7); fma2(acc[3][7], s23.y, w7);
                }
            }
        }
        __syncthreads();
    }

    // ---- consumer epilogue: out[b][og*8+o][h][pg*8 .. +7] -------------------
    if (!producer) {
        float* op = out + (((size_t)(b * COUT + og * 8) * HD + h) * WD) + pg * 8;
        #pragma unroll
        for (int o = 0; o < 8; ++o) {
            float2 a0 = unpack2(acc[0][o]);
            float2 a1 = unpack2(acc[1][o]);
            float2 a2 = unpack2(acc[2][o]);
            float2 a3 = unpack2(acc[3][o]);
            *(float4*)(op + (size_t)o * HW)     = make_float4(a0.x, a0.y, a1.x, a1.y);
            *(float4*)(op + (size_t)o * HW + 4) = make_float4(a2.x, a2.y, a3.x, a3.y);
        }
    }
}

// ------------------------------- launch -------------------------------------
extern "C" void kernel_launch(void* const* d_in, const int* in_sizes, int n_in,
                              void* d_out, int out_size) {
    const float* x     = (const float*)d_in[0];
    const float* w_off = (const float*)d_in[1];
    const float* b_off = (const float*)d_in[2];
    const float* w_def = (const float*)d_in[3];
    float* out = (float*)d_out;

    (void)cudaFuncSetAttribute(k_fused, cudaFuncAttributeMaxDynamicSharedMemorySize, SMEM_FUSED);

    k_tr      <<<dim3(HW / 64, BD), 256>>>(x);
    k_prep_w  <<<(KK * CIN * COUT + 255) / 256, 256>>>(w_def);
    k_prep_off<<<(576 * 9 + 255) / 256, 256>>>(w_off);
    k_fused   <<<dim3(HD, BD), 384, SMEM_FUSED>>>(x, b_off, out);
}